// round 11
// baseline (speedup 1.0000x reference)
#include <cuda_runtime.h>
#include <cuda_bf16.h>
#include <math.h>
#include <stdlib.h>
#include <stdint.h>

#define NN 50000
#define NE 640000
#define NG 64
#define HD 128
#define INF 8
#define BN_EPS 1e-5f
#define TILE 64

// Best-effort eager module loading (kept from passing rounds).
__attribute__((constructor))
static void _set_eager_module_loading() {
    setenv("CUDA_MODULE_LOADING", "EAGER", 1);
}

// ---------------- scratch (static __device__; ~54 MB) ------------------------
__device__ float g_bufA[NN * HD];          // h1
__device__ float g_bufB[NN * HD];          // h2 (h3 never materialized)
__device__ int   g_deg[NN];
__device__ int   g_rowptr[NN + 1];
__device__ int   g_cursor[NN];
__device__ int   g_col[NE];
__device__ float g_pooled[NG * 384];

namespace {
struct TryEagerLoad {
    TryEagerLoad() { void* p = nullptr; cudaGetSymbolAddress(&p, g_bufA); }
};
static TryEagerLoad _try_eager_load;
}

// ---------------- mma.sync tf32 helpers (portable sm_80+) --------------------
__device__ __forceinline__ void mma_tf32(float* c,
        uint32_t a0, uint32_t a1, uint32_t a2, uint32_t a3,
        uint32_t b0, uint32_t b1) {
    asm volatile(
        "mma.sync.aligned.m16n8k8.row.col.f32.tf32.tf32.f32 "
        "{%0,%1,%2,%3}, {%4,%5,%6,%7}, {%8,%9}, {%0,%1,%2,%3};"
        : "+f"(c[0]), "+f"(c[1]), "+f"(c[2]), "+f"(c[3])
        : "r"(a0), "r"(a1), "r"(a2), "r"(a3), "r"(b0), "r"(b1));
}

// 3xTF32 split: x ~= hi + lo, both tf32-representable fp32 bit patterns.
__device__ __forceinline__ void split_tf32(float x, uint32_t& hi, uint32_t& lo) {
    asm("cvt.rna.tf32.f32 %0, %1;" : "=r"(hi) : "f"(x));
    float r = x - __uint_as_float(hi);
    asm("cvt.rna.tf32.f32 %0, %1;" : "=r"(lo) : "f"(r));
}

// ---------------- CSR ----------------
__global__ void count_kernel(const int* __restrict__ eidx) {
    int e = blockIdx.x * blockDim.x + threadIdx.x;
    if (e < NE) atomicAdd(&g_deg[eidx[NE + e]], 1);
}

// single-block shuffle scan over 50000 degrees -> rowptr, cursor(=exclusive)
__global__ void scan_kernel() {
    __shared__ int wsum[32];
    __shared__ int s_carry;
    int tid = threadIdx.x, lane = tid & 31, w = tid >> 5;
    if (tid == 0) { s_carry = 0; g_rowptr[0] = 0; }
    __syncthreads();
    for (int base = 0; base < NN; base += 1024) {
        int i = base + tid;
        int v = (i < NN) ? g_deg[i] : 0;
        int x = v;
        #pragma unroll
        for (int d = 1; d < 32; d <<= 1) {
            int t = __shfl_up_sync(~0u, x, d);
            if (lane >= d) x += t;
        }
        if (lane == 31) wsum[w] = x;
        __syncthreads();
        if (w == 0) {
            int y = wsum[lane];
            #pragma unroll
            for (int d = 1; d < 32; d <<= 1) {
                int t = __shfl_up_sync(~0u, y, d);
                if (lane >= d) y += t;
            }
            wsum[lane] = y;
        }
        __syncthreads();
        int inc = x + (w > 0 ? wsum[w - 1] : 0) + s_carry;
        if (i < NN) { g_rowptr[i + 1] = inc; g_cursor[i] = inc - v; }
        __syncthreads();
        if (tid == 1023) s_carry = inc;
        __syncthreads();
    }
}

__global__ void fill_kernel(const int* __restrict__ eidx) {
    int e = blockIdx.x * blockDim.x + threadIdx.x;
    if (e < NE) {
        int src = eidx[e];
        int dst = eidx[NE + e];
        g_col[atomicAdd(&g_cursor[dst], 1)] = src;
    }
}

// ---------------- fused GIN layer (mma.sync tf32x3, row-quad gather) ---------
// 256 threads; 64-node tile; 8 warps each own a 16x64 output block.
// Gather: each 4-lane quad owns one row; lane q covers features
// [q*32, q*32+32) as 8 float4s. A warp drives 8 rows' edge loops
// CONCURRENTLY -> ~64 loads in flight vs ~4 in the serial version.
template <int FIN, int SLICE, bool WRITE>
__global__ void __launch_bounds__(256, 2)
gin_layer(const float* __restrict__ src,
          const float* __restrict__ W1, const float* __restrict__ b1,
          const float* __restrict__ W2, const float* __restrict__ b2,
          const int* __restrict__ batch,
          float* __restrict__ out, int n) {
    extern __shared__ float smem[];
    float* sW  = smem;                       // 128*132 (W1, later W2)
    float* sIO = sW + 128 * 132;             // 64*132
    float* b1s = sIO + TILE * 132;
    float* b2s = b1s + 128;
    int*   sBatch = (int*)(b2s + 128);

    const int tid  = threadIdx.x;
    const int lane = tid & 31;
    const int wid  = tid >> 5;               // 8 warps
    const int node0 = blockIdx.x * TILE;

    // load W1 [FIN][128] -> sW (stride 132)
    for (int i = tid; i < FIN * 32; i += 256) {
        int k = i >> 5, c = i & 31;
        *(float4*)&sW[k * 132 + c * 4] = ((const float4*)W1)[i];
    }
    if (tid < 128) {
        b1s[tid] = b1[tid];
        b2s[tid] = b2[tid];
    }
    if (tid < TILE) {
        int node = node0 + tid;
        sBatch[tid] = batch[node < n ? node : (n - 1)];
    }

    // ---- gather: sIO[r][:] = src[node] + sum_neighbors ----
    if (FIN == 128) {
        const float4* src4 = (const float4*)src;
        const int rsub = lane >> 2;          // 0..7: row within warp's 8 rows
        const int q    = lane & 3;           // 0..3: feature quarter (8 float4s)
        const int r    = wid * 8 + rsub;
        const int node = node0 + r;
        float4 acc[8];
        #pragma unroll
        for (int t = 0; t < 8; t++) acc[t] = make_float4(0.f, 0.f, 0.f, 0.f);
        if (node < n) {
            const float4* base = src4 + node * 32 + q * 8;
            #pragma unroll
            for (int t = 0; t < 8; t++) acc[t] = base[t];
            int s = g_rowptr[node], e = g_rowptr[node + 1];
            for (int j = s; j < e; j++) {
                const float4* nb = src4 + g_col[j] * 32 + q * 8;
                #pragma unroll
                for (int t = 0; t < 8; t++) {
                    float4 v = nb[t];
                    acc[t].x += v.x; acc[t].y += v.y;
                    acc[t].z += v.z; acc[t].w += v.w;
                }
            }
        }
        float4* dst = (float4*)&sIO[r * 132 + q * 32];
        #pragma unroll
        for (int t = 0; t < 8; t++) dst[t] = acc[t];
    } else {  // FIN == 8: one row per warp iteration, lanes 0-1 cover 8 floats
        const float4* src4 = (const float4*)src;
        for (int r0i = wid; r0i < TILE; r0i += 8) {
            if (lane < 2) {
                int node = node0 + r0i;
                float4 acc = make_float4(0.f, 0.f, 0.f, 0.f);
                if (node < n) {
                    acc = src4[node * 2 + lane];
                    int s = g_rowptr[node], e = g_rowptr[node + 1];
                    #pragma unroll 4
                    for (int j = s; j < e; j++) {
                        float4 v = src4[g_col[j] * 2 + lane];
                        acc.x += v.x; acc.y += v.y; acc.z += v.z; acc.w += v.w;
                    }
                }
                *(float4*)&sIO[r0i * 132 + lane * 4] = acc;
            }
        }
    }
    __syncthreads();

    // warp tiling: rows [row0, row0+16), cols [col0, col0+64)
    const int row0 = (wid >> 1) * 16;        // 0,16,32,48
    const int col0 = (wid & 1) * 64;
    const int qr = lane >> 2;   // 0..7
    const int qc = lane & 3;    // 0..3

    float acc[8][4];

    // ---- stage A: acc = sIO @ W1 + b1 (3xTF32, on-the-fly splits) ----
    #pragma unroll
    for (int nt = 0; nt < 8; nt++) {
        int c = col0 + nt * 8 + 2 * qc;
        acc[nt][0] = b1s[c];     acc[nt][1] = b1s[c + 1];
        acc[nt][2] = b1s[c];     acc[nt][3] = b1s[c + 1];
    }
    #pragma unroll
    for (int ks = 0; ks < FIN / 8; ks++) {
        int k0 = ks * 8;
        float a0f = sIO[(row0 + qr)     * 132 + k0 + qc];
        float a1f = sIO[(row0 + qr + 8) * 132 + k0 + qc];
        float a2f = sIO[(row0 + qr)     * 132 + k0 + qc + 4];
        float a3f = sIO[(row0 + qr + 8) * 132 + k0 + qc + 4];
        uint32_t ah0, al0, ah1, al1, ah2, al2, ah3, al3;
        split_tf32(a0f, ah0, al0); split_tf32(a1f, ah1, al1);
        split_tf32(a2f, ah2, al2); split_tf32(a3f, ah3, al3);
        #pragma unroll
        for (int nt = 0; nt < 8; nt++) {
            int bn = col0 + nt * 8 + qr;
            float b0f = sW[(k0 + qc)     * 132 + bn];
            float b1f = sW[(k0 + qc + 4) * 132 + bn];
            uint32_t bh0, bl0, bh1, bl1;
            split_tf32(b0f, bh0, bl0); split_tf32(b1f, bh1, bl1);
            mma_tf32(acc[nt], ah0, ah1, ah2, ah3, bh0, bh1);
            mma_tf32(acc[nt], ah0, ah1, ah2, ah3, bl0, bl1);
            mma_tf32(acc[nt], al0, al1, al2, al3, bh0, bh1);
        }
    }
    __syncthreads();  // all stage-A reads of sIO and sW complete

    // write stage-A relu output back into sIO; load W2 over sW
    #pragma unroll
    for (int nt = 0; nt < 8; nt++) {
        int c = col0 + nt * 8 + 2 * qc;
        int r = row0 + qr;
        sIO[r * 132 + c]           = fmaxf(acc[nt][0], 0.f);
        sIO[r * 132 + c + 1]       = fmaxf(acc[nt][1], 0.f);
        sIO[(r + 8) * 132 + c]     = fmaxf(acc[nt][2], 0.f);
        sIO[(r + 8) * 132 + c + 1] = fmaxf(acc[nt][3], 0.f);
    }
    for (int i = tid; i < 4096; i += 256) {
        int k = i >> 5, c = i & 31;
        *(float4*)&sW[k * 132 + c * 4] = ((const float4*)W2)[i];
    }
    __syncthreads();

    // ---- stage B: acc = sIO @ W2 + b2 (3xTF32) ----
    #pragma unroll
    for (int nt = 0; nt < 8; nt++) {
        int c = col0 + nt * 8 + 2 * qc;
        acc[nt][0] = b2s[c];     acc[nt][1] = b2s[c + 1];
        acc[nt][2] = b2s[c];     acc[nt][3] = b2s[c + 1];
    }
    #pragma unroll
    for (int ks = 0; ks < 16; ks++) {
        int k0 = ks * 8;
        float a0f = sIO[(row0 + qr)     * 132 + k0 + qc];
        float a1f = sIO[(row0 + qr + 8) * 132 + k0 + qc];
        float a2f = sIO[(row0 + qr)     * 132 + k0 + qc + 4];
        float a3f = sIO[(row0 + qr + 8) * 132 + k0 + qc + 4];
        uint32_t ah0, al0, ah1, al1, ah2, al2, ah3, al3;
        split_tf32(a0f, ah0, al0); split_tf32(a1f, ah1, al1);
        split_tf32(a2f, ah2, al2); split_tf32(a3f, ah3, al3);
        #pragma unroll
        for (int nt = 0; nt < 8; nt++) {
            int bn = col0 + nt * 8 + qr;
            float b0f = sW[(k0 + qc)     * 132 + bn];
            float b1f = sW[(k0 + qc + 4) * 132 + bn];
            uint32_t bh0, bl0, bh1, bl1;
            split_tf32(b0f, bh0, bl0); split_tf32(b1f, bh1, bl1);
            mma_tf32(acc[nt], ah0, ah1, ah2, ah3, bh0, bh1);
            mma_tf32(acc[nt], ah0, ah1, ah2, ah3, bl0, bl1);
            mma_tf32(acc[nt], al0, al1, al2, al3, bh0, bh1);
        }
    }
    __syncthreads();  // all stage-B reads of sIO complete before overwrite

    // epilogue: relu, zero invalid rows, stash final tile in sIO
    {
        int rA = row0 + qr, rB = row0 + qr + 8;
        bool vA = (node0 + rA) < n, vB = (node0 + rB) < n;
        #pragma unroll
        for (int nt = 0; nt < 8; nt++) {
            int c = col0 + nt * 8 + 2 * qc;
            sIO[rA * 132 + c]     = vA ? fmaxf(acc[nt][0], 0.f) : 0.f;
            sIO[rA * 132 + c + 1] = vA ? fmaxf(acc[nt][1], 0.f) : 0.f;
            sIO[rB * 132 + c]     = vB ? fmaxf(acc[nt][2], 0.f) : 0.f;
            sIO[rB * 132 + c + 1] = vB ? fmaxf(acc[nt][3], 0.f) : 0.f;
        }
    }
    __syncthreads();

    // pooling: thread f sums its feature column over sorted-batch segments
    if (tid < 128) {
        int f = tid;
        float pacc = sIO[f];
        int curg = sBatch[0];
        for (int r = 1; r < TILE; r++) {
            int g = sBatch[r];
            if (g != curg) {
                atomicAdd(&g_pooled[curg * 384 + SLICE + f], pacc);
                pacc = 0.f;
                curg = g;
            }
            pacc += sIO[r * 132 + f];
        }
        atomicAdd(&g_pooled[curg * 384 + SLICE + f], pacc);
    }

    // coalesced float4 writeback
    if (WRITE) {
        float4* out4 = (float4*)out;
        for (int idx = tid; idx < TILE * 32; idx += 256) {
            int r = idx >> 5, c4 = idx & 31;
            int node = node0 + r;
            if (node < n)
                out4[node * 32 + c4] = *(float4*)&sIO[r * 132 + c4 * 4];
        }
    }
}

// ---------------- classifier (also re-arms g_deg / g_pooled for next replay) -
__global__ void cls_kernel(const float* __restrict__ W1, const float* __restrict__ b1,
                           const float* __restrict__ gamma, const float* __restrict__ beta,
                           const float* __restrict__ mean, const float* __restrict__ var,
                           const float* __restrict__ W2, const float* __restrict__ b2,
                           float* __restrict__ out) {
    __shared__ float sp[384];
    __shared__ float sz[256];
    int g = blockIdx.x;
    int tid = threadIdx.x;  // 0..255
    // zero g_deg for the NEXT launch cycle (64 blocks x 256 threads grid-stride)
    for (int i = g * 256 + tid; i < NN; i += NG * 256) g_deg[i] = 0;
    for (int i = tid; i < 384; i += 256) sp[i] = g_pooled[g * 384 + i];
    __syncthreads();
    // re-zero this graph's pooled slice for the next launch cycle
    for (int i = tid; i < 384; i += 256) g_pooled[g * 384 + i] = 0.f;
    float acc = b1[tid];
    #pragma unroll 8
    for (int k = 0; k < 384; k++) acc += sp[k] * W1[k * 256 + tid];
    float z = (acc - mean[tid]) * rsqrtf(var[tid] + BN_EPS) * gamma[tid] + beta[tid];
    sz[tid] = fmaxf(z, 0.f);
    __syncthreads();
    if (tid < 4) {
        float o = b2[tid];
        #pragma unroll 8
        for (int k = 0; k < 256; k++) o += sz[k] * W2[k * 4 + tid];
        out[g * 4 + tid] = o;
    }
}

// ---------------- launch ----------------
extern "C" void kernel_launch(void* const* d_in, const int* in_sizes, int n_in,
                              void* d_out, int out_size) {
    const float* x     = (const float*)d_in[0];
    const int*   eidx  = (const int*)d_in[1];
    const int*   batch = (const int*)d_in[2];
    const float* l1_W1 = (const float*)d_in[3];
    const float* l1_b1 = (const float*)d_in[4];
    const float* l1_W2 = (const float*)d_in[5];
    const float* l1_b2 = (const float*)d_in[6];
    const float* l2_W1 = (const float*)d_in[7];
    const float* l2_b1 = (const float*)d_in[8];
    const float* l2_W2 = (const float*)d_in[9];
    const float* l2_b2 = (const float*)d_in[10];
    const float* l3_W1 = (const float*)d_in[11];
    const float* l3_b1 = (const float*)d_in[12];
    const float* l3_W2 = (const float*)d_in[13];
    const float* l3_b2 = (const float*)d_in[14];
    const float* c_W1  = (const float*)d_in[15];
    const float* c_b1  = (const float*)d_in[16];
    const float* bn_g  = (const float*)d_in[17];
    const float* bn_b  = (const float*)d_in[18];
    const float* bn_m  = (const float*)d_in[19];
    const float* bn_v  = (const float*)d_in[20];
    const float* c_W2  = (const float*)d_in[21];
    const float* c_b2  = (const float*)d_in[22];
    float* out = (float*)d_out;

    // smem: sW(128*132) + sIO(64*132) + b1s/b2s(256) + batch(64)
    const int SMEM = (128 * 132 + TILE * 132 + 256 + TILE) * 4 + 256;  // ~102.9 KB
    cudaFuncSetAttribute(gin_layer<8, 0, true>,
                         cudaFuncAttributeMaxDynamicSharedMemorySize, SMEM);
    cudaFuncSetAttribute(gin_layer<128, 128, true>,
                         cudaFuncAttributeMaxDynamicSharedMemorySize, SMEM);
    cudaFuncSetAttribute(gin_layer<128, 256, false>,
                         cudaFuncAttributeMaxDynamicSharedMemorySize, SMEM);

    float *bufA, *bufB;
    cudaGetSymbolAddress((void**)&bufA, g_bufA);
    cudaGetSymbolAddress((void**)&bufB, g_bufB);

    // CSR (g_deg arrives zeroed: BSS on first run, cls_kernel thereafter)
    count_kernel<<<(NE + 255) / 256, 256>>>(eidx);
    scan_kernel<<<1, 1024>>>();
    fill_kernel<<<(NE + 255) / 256, 256>>>(eidx);

    const int GRID = (NN + TILE - 1) / TILE;  // 782

    gin_layer<8, 0, true><<<GRID, 256, SMEM>>>(
        x, l1_W1, l1_b1, l1_W2, l1_b2, batch, bufA, NN);
    gin_layer<128, 128, true><<<GRID, 256, SMEM>>>(
        bufA, l2_W1, l2_b1, l2_W2, l2_b2, batch, bufB, NN);
    gin_layer<128, 256, false><<<GRID, 256, SMEM>>>(
        bufB, l3_W1, l3_b1, l3_W2, l3_b2, batch, nullptr, NN);

    cls_kernel<<<NG, 256>>>(c_W1, c_b1, bn_g, bn_b, bn_m, bn_v, c_W2, c_b2, out);
}

// round 12
// speedup vs baseline: 1.6051x; 1.6051x over previous
#include <cuda_runtime.h>
#include <cuda_bf16.h>
#include <math.h>
#include <stdlib.h>
#include <stdint.h>

#define NN 50000
#define NE 640000
#define NG 64
#define HD 128
#define INF 8
#define BN_EPS 1e-5f
#define TILE 64
#define WSTRIDE 136   // word stride of packed-W smem rows (bank: 8qc+qr distinct)
#define ASTRIDE 68    // word stride of packed-A smem rows (bank: 4qr+qc distinct)
#define OSTRIDE 132   // word stride of fp32 output tile

// Best-effort eager module loading (kept from passing rounds).
__attribute__((constructor))
static void _set_eager_module_loading() {
    setenv("CUDA_MODULE_LOADING", "EAGER", 1);
}

// ---------------- scratch (static __device__; ~55 MB) ------------------------
__device__ float    g_bufA[NN * HD];       // h1
__device__ float    g_bufB[NN * HD];       // h2 (h3 never materialized)
__device__ int      g_deg[NN];
__device__ int      g_rowptr[NN + 1];
__device__ int      g_cursor[NN];
__device__ int      g_col[NE];
__device__ float    g_pooled[NG * 384];
// packed bf16x2 weight images: [matrix 0..5][pair][n], pair = k/2
// matrix 0 = l1_W1 (8 pairs incl. zero-pad to K16); 1..5 = 64 pairs each
__device__ uint32_t g_wp_hi[6][64 * 128];
__device__ uint32_t g_wp_lo[6][64 * 128];

namespace {
struct TryEagerLoad {
    TryEagerLoad() { void* p = nullptr; cudaGetSymbolAddress(&p, g_bufA); }
};
static TryEagerLoad _try_eager_load;
}

// ---------------- bf16 helpers ----------------
// pack2(even_k, odd_k): bf16x2 register, LOW half = even-k element.
__device__ __forceinline__ uint32_t pack2(float even, float odd) {
    uint32_t r;
    asm("cvt.rn.satfinite.bf16x2.f32 %0, %1, %2;" : "=r"(r) : "f"(odd), "f"(even));
    return r;
}
__device__ __forceinline__ float lo_f(uint32_t h) { return __uint_as_float(h << 16); }
__device__ __forceinline__ float hi_f(uint32_t h) { return __uint_as_float(h & 0xFFFF0000u); }
// 3-term split: value = hi + lo (both bf16); missing term in products ~2^-18.
__device__ __forceinline__ void pack3(float even, float odd, uint32_t& hi, uint32_t& lo) {
    hi = pack2(even, odd);
    lo = pack2(even - lo_f(hi), odd - hi_f(hi));
}

__device__ __forceinline__ void mma_bf16(float* c,
        uint32_t a0, uint32_t a1, uint32_t a2, uint32_t a3,
        uint32_t b0, uint32_t b1) {
    asm volatile(
        "mma.sync.aligned.m16n8k16.row.col.f32.bf16.bf16.f32 "
        "{%0,%1,%2,%3}, {%4,%5,%6,%7}, {%8,%9}, {%0,%1,%2,%3};"
        : "+f"(c[0]), "+f"(c[1]), "+f"(c[2]), "+f"(c[3])
        : "r"(a0), "r"(a1), "r"(a2), "r"(a3), "r"(b0), "r"(b1));
}

// ---------------- CSR ----------------
__global__ void count_kernel(const int* __restrict__ eidx) {
    int e = blockIdx.x * blockDim.x + threadIdx.x;
    if (e < NE) atomicAdd(&g_deg[eidx[NE + e]], 1);
}

__global__ void scan_kernel() {
    __shared__ int wsum[32];
    __shared__ int s_carry;
    int tid = threadIdx.x, lane = tid & 31, w = tid >> 5;
    if (tid == 0) { s_carry = 0; g_rowptr[0] = 0; }
    __syncthreads();
    for (int base = 0; base < NN; base += 1024) {
        int i = base + tid;
        int v = (i < NN) ? g_deg[i] : 0;
        int x = v;
        #pragma unroll
        for (int d = 1; d < 32; d <<= 1) {
            int t = __shfl_up_sync(~0u, x, d);
            if (lane >= d) x += t;
        }
        if (lane == 31) wsum[w] = x;
        __syncthreads();
        if (w == 0) {
            int y = wsum[lane];
            #pragma unroll
            for (int d = 1; d < 32; d <<= 1) {
                int t = __shfl_up_sync(~0u, y, d);
                if (lane >= d) y += t;
            }
            wsum[lane] = y;
        }
        __syncthreads();
        int inc = x + (w > 0 ? wsum[w - 1] : 0) + s_carry;
        if (i < NN) { g_rowptr[i + 1] = inc; g_cursor[i] = inc - v; }
        __syncthreads();
        if (tid == 1023) s_carry = inc;
        __syncthreads();
    }
}

__global__ void fill_kernel(const int* __restrict__ eidx) {
    int e = blockIdx.x * blockDim.x + threadIdx.x;
    if (e < NE) {
        int src = eidx[e];
        int dst = eidx[NE + e];
        g_col[atomicAdd(&g_cursor[dst], 1)] = src;
    }
}

// ---------------- weight packing: W[k][n] fp32 -> bf16x2 hi/lo pair images ---
__global__ void pack_all(const float* __restrict__ w0, const float* __restrict__ w1,
                         const float* __restrict__ w2, const float* __restrict__ w3,
                         const float* __restrict__ w4, const float* __restrict__ w5) {
    int m = blockIdx.y;
    const float* Ws[6] = {w0, w1, w2, w3, w4, w5};
    const float* W = Ws[m];
    int K  = (m == 0) ? 8 : 128;
    int PO = (m == 0) ? 8 : 64;    // pairs emitted (zero-padded beyond K/2)
    int total = PO * 128;
    for (int idx = blockIdx.x * 256 + threadIdx.x; idx < total; idx += gridDim.x * 256) {
        int p = idx >> 7, nn = idx & 127;
        float f0 = 0.f, f1 = 0.f;
        if (2 * p < K) {
            f0 = W[(2 * p) * 128 + nn];
            f1 = W[(2 * p + 1) * 128 + nn];
        }
        uint32_t h, l;
        pack3(f0, f1, h, l);
        g_wp_hi[m][idx] = h;
        g_wp_lo[m][idx] = l;
    }
}

// ---------------- fused GIN layer (mma.sync bf16x3 m16n8k16) -----------------
// 256 threads; 64-node tile; 8 warps each own a 16x64 output block.
// smem: sWhi/sWlo [64][WSTRIDE] | sAhi/sAlo [64][ASTRIDE] | biases | batch
// Inner loop is pure LDS + MMA: all bf16 splits happen at producers.
template <int FIN, int SLICE, bool WRITE>
__global__ void __launch_bounds__(256, 2)
gin_layer(const float* __restrict__ src,
          const uint32_t* __restrict__ W1h, const uint32_t* __restrict__ W1l,
          const float* __restrict__ b1,
          const uint32_t* __restrict__ W2h, const uint32_t* __restrict__ W2l,
          const float* __restrict__ b2,
          const int* __restrict__ batch,
          float* __restrict__ out, int n) {
    extern __shared__ uint32_t smem_u[];
    uint32_t* sWhi = smem_u;                       // 64*WSTRIDE
    uint32_t* sWlo = sWhi + 64 * WSTRIDE;
    uint32_t* sAhi = sWlo + 64 * WSTRIDE;          // 64*ASTRIDE
    uint32_t* sAlo = sAhi + 64 * ASTRIDE;
    float*    sOut = (float*)sAhi;                 // 64*OSTRIDE fp32 (reuses A region)
    float*    b1s  = (float*)(sAlo + 64 * ASTRIDE);
    float*    b2s  = b1s + 128;
    int*      sBatch = (int*)(b2s + 128);

    const int tid  = threadIdx.x;
    const int lane = tid & 31;
    const int wid  = tid >> 5;                     // 8 warps
    const int node0 = blockIdx.x * TILE;

    // copy packed W1 (P1 pairs) into smem
    constexpr int P1 = (FIN == 8) ? 8 : 64;
    for (int i = tid; i < P1 * 32; i += 256) {
        int p = i >> 5, c4 = i & 31;
        ((uint4*)&sWhi[p * WSTRIDE])[c4] = ((const uint4*)&W1h[p * 128])[c4];
        ((uint4*)&sWlo[p * WSTRIDE])[c4] = ((const uint4*)&W1l[p * 128])[c4];
    }
    if (tid < 128) {
        b1s[tid] = b1[tid];
        b2s[tid] = b2[tid];
    }
    if (tid < TILE) {
        int node = node0 + tid;
        sBatch[tid] = batch[node < n ? node : (n - 1)];
    }

    // ---- gather (R9-style) + inline bf16x3 packing into sAhi/sAlo ----
    if (FIN == 128) {
        const float4* src4 = (const float4*)src;
        for (int r = wid; r < TILE; r += 8) {
            int node = node0 + r;
            float4 acc = make_float4(0.f, 0.f, 0.f, 0.f);
            if (node < n) {
                acc = src4[node * 32 + lane];
                int s = g_rowptr[node], e = g_rowptr[node + 1];
                #pragma unroll 4
                for (int j = s; j < e; j++) {
                    float4 v = src4[g_col[j] * 32 + lane];
                    acc.x += v.x; acc.y += v.y; acc.z += v.z; acc.w += v.w;
                }
            }
            uint32_t h0, l0, h1, l1;
            pack3(acc.x, acc.y, h0, l0);   // pair 2*lane   (k = 4*lane, 4*lane+1)
            pack3(acc.z, acc.w, h1, l1);   // pair 2*lane+1 (k = 4*lane+2, +3)
            *(uint2*)&sAhi[r * ASTRIDE + 2 * lane] = make_uint2(h0, h1);
            *(uint2*)&sAlo[r * ASTRIDE + 2 * lane] = make_uint2(l0, l1);
        }
    } else {  // FIN == 8: lanes 0-1 gather 8 feats (pairs 0..3); lanes 2-3 zero-pad 4..7
        const float4* src4 = (const float4*)src;
        for (int r = wid; r < TILE; r += 8) {
            if (lane < 2) {
                int node = node0 + r;
                float4 acc = make_float4(0.f, 0.f, 0.f, 0.f);
                if (node < n) {
                    acc = src4[node * 2 + lane];
                    int s = g_rowptr[node], e = g_rowptr[node + 1];
                    #pragma unroll 4
                    for (int j = s; j < e; j++) {
                        float4 v = src4[g_col[j] * 2 + lane];
                        acc.x += v.x; acc.y += v.y; acc.z += v.z; acc.w += v.w;
                    }
                }
                uint32_t h0, l0, h1, l1;
                pack3(acc.x, acc.y, h0, l0);
                pack3(acc.z, acc.w, h1, l1);
                *(uint2*)&sAhi[r * ASTRIDE + 2 * lane] = make_uint2(h0, h1);
                *(uint2*)&sAlo[r * ASTRIDE + 2 * lane] = make_uint2(l0, l1);
            } else if (lane < 4) {
                *(uint2*)&sAhi[r * ASTRIDE + 2 * lane] = make_uint2(0u, 0u);
                *(uint2*)&sAlo[r * ASTRIDE + 2 * lane] = make_uint2(0u, 0u);
            }
        }
    }
    __syncthreads();

    // warp tiling: rows [row0, row0+16), cols [col0, col0+64)
    const int row0 = (wid >> 1) * 16;
    const int col0 = (wid & 1) * 64;
    const int qr = lane >> 2;   // 0..7
    const int qc = lane & 3;    // 0..3

    float acc[8][4];

    // ---- stage A: acc = A @ W1 + b1 (bf16x3) ----
    #pragma unroll
    for (int nt = 0; nt < 8; nt++) {
        int c = col0 + nt * 8 + 2 * qc;
        acc[nt][0] = b1s[c];     acc[nt][1] = b1s[c + 1];
        acc[nt][2] = b1s[c];     acc[nt][3] = b1s[c + 1];
    }
    constexpr int KS1 = (FIN == 8) ? 1 : 8;
    #pragma unroll
    for (int ks = 0; ks < KS1; ks++) {
        int pb = ks * 8;
        const uint32_t* aHr = &sAhi[(row0 + qr) * ASTRIDE + pb];
        const uint32_t* aLr = &sAlo[(row0 + qr) * ASTRIDE + pb];
        uint32_t a0h = aHr[qc],              a2h = aHr[qc + 4];
        uint32_t a1h = aHr[8 * ASTRIDE + qc], a3h = aHr[8 * ASTRIDE + qc + 4];
        uint32_t a0l = aLr[qc],              a2l = aLr[qc + 4];
        uint32_t a1l = aLr[8 * ASTRIDE + qc], a3l = aLr[8 * ASTRIDE + qc + 4];
        #pragma unroll
        for (int nt = 0; nt < 8; nt++) {
            int bn = col0 + nt * 8 + qr;
            uint32_t b0h = sWhi[(pb + qc) * WSTRIDE + bn];
            uint32_t b1h = sWhi[(pb + qc + 4) * WSTRIDE + bn];
            uint32_t b0l = sWlo[(pb + qc) * WSTRIDE + bn];
            uint32_t b1l = sWlo[(pb + qc + 4) * WSTRIDE + bn];
            mma_bf16(acc[nt], a0h, a1h, a2h, a3h, b0h, b1h);
            mma_bf16(acc[nt], a0h, a1h, a2h, a3h, b0l, b1l);
            mma_bf16(acc[nt], a0l, a1l, a2l, a3l, b0h, b1h);
        }
    }
    __syncthreads();  // all stage-A reads of sA and sW complete

    // epilogue A: relu + pack back into sAhi/sAlo; load packed W2 over sW
    #pragma unroll
    for (int nt = 0; nt < 8; nt++) {
        int p  = (col0 >> 1) + nt * 4 + qc;    // output pair index (c, c+1)
        int rA = row0 + qr, rB = rA + 8;
        float v0 = fmaxf(acc[nt][0], 0.f), v1 = fmaxf(acc[nt][1], 0.f);
        float v2 = fmaxf(acc[nt][2], 0.f), v3 = fmaxf(acc[nt][3], 0.f);
        uint32_t h, l;
        pack3(v0, v1, h, l);
        sAhi[rA * ASTRIDE + p] = h;  sAlo[rA * ASTRIDE + p] = l;
        pack3(v2, v3, h, l);
        sAhi[rB * ASTRIDE + p] = h;  sAlo[rB * ASTRIDE + p] = l;
    }
    for (int i = tid; i < 64 * 32; i += 256) {
        int p = i >> 5, c4 = i & 31;
        ((uint4*)&sWhi[p * WSTRIDE])[c4] = ((const uint4*)&W2h[p * 128])[c4];
        ((uint4*)&sWlo[p * WSTRIDE])[c4] = ((const uint4*)&W2l[p * 128])[c4];
    }
    __syncthreads();

    // ---- stage B: acc = A2 @ W2 + b2 (bf16x3) ----
    #pragma unroll
    for (int nt = 0; nt < 8; nt++) {
        int c = col0 + nt * 8 + 2 * qc;
        acc[nt][0] = b2s[c];     acc[nt][1] = b2s[c + 1];
        acc[nt][2] = b2s[c];     acc[nt][3] = b2s[c + 1];
    }
    #pragma unroll
    for (int ks = 0; ks < 8; ks++) {
        int pb = ks * 8;
        const uint32_t* aHr = &sAhi[(row0 + qr) * ASTRIDE + pb];
        const uint32_t* aLr = &sAlo[(row0 + qr) * ASTRIDE + pb];
        uint32_t a0h = aHr[qc],              a2h = aHr[qc + 4];
        uint32_t a1h = aHr[8 * ASTRIDE + qc], a3h = aHr[8 * ASTRIDE + qc + 4];
        uint32_t a0l = aLr[qc],              a2l = aLr[qc + 4];
        uint32_t a1l = aLr[8 * ASTRIDE + qc], a3l = aLr[8 * ASTRIDE + qc + 4];
        #pragma unroll
        for (int nt = 0; nt < 8; nt++) {
            int bn = col0 + nt * 8 + qr;
            uint32_t b0h = sWhi[(pb + qc) * WSTRIDE + bn];
            uint32_t b1h = sWhi[(pb + qc + 4) * WSTRIDE + bn];
            uint32_t b0l = sWlo[(pb + qc) * WSTRIDE + bn];
            uint32_t b1l = sWlo[(pb + qc + 4) * WSTRIDE + bn];
            mma_bf16(acc[nt], a0h, a1h, a2h, a3h, b0h, b1h);
            mma_bf16(acc[nt], a0h, a1h, a2h, a3h, b0l, b1l);
            mma_bf16(acc[nt], a0l, a1l, a2l, a3l, b0h, b1h);
        }
    }
    __syncthreads();  // all stage-B reads of sA complete before fp32 overwrite

    // epilogue B: relu, zero invalid rows, store fp32 tile into sOut
    {
        int rA = row0 + qr, rB = rA + 8;
        bool vA = (node0 + rA) < n, vB = (node0 + rB) < n;
        #pragma unroll
        for (int nt = 0; nt < 8; nt++) {
            int c = col0 + nt * 8 + 2 * qc;
            sOut[rA * OSTRIDE + c]     = vA ? fmaxf(acc[nt][0], 0.f) : 0.f;
            sOut[rA * OSTRIDE + c + 1] = vA ? fmaxf(acc[nt][1], 0.f) : 0.f;
            sOut[rB * OSTRIDE + c]     = vB ? fmaxf(acc[nt][2], 0.f) : 0.f;
            sOut[rB * OSTRIDE + c + 1] = vB ? fmaxf(acc[nt][3], 0.f) : 0.f;
        }
    }
    __syncthreads();

    // pooling: thread f sums its feature column over sorted-batch segments
    if (tid < 128) {
        int f = tid;
        float pacc = sOut[f];
        int curg = sBatch[0];
        for (int r = 1; r < TILE; r++) {
            int g = sBatch[r];
            if (g != curg) {
                atomicAdd(&g_pooled[curg * 384 + SLICE + f], pacc);
                pacc = 0.f;
                curg = g;
            }
            pacc += sOut[r * OSTRIDE + f];
        }
        atomicAdd(&g_pooled[curg * 384 + SLICE + f], pacc);
    }

    // coalesced float4 writeback
    if (WRITE) {
        float4* out4 = (float4*)out;
        for (int idx = tid; idx < TILE * 32; idx += 256) {
            int r = idx >> 5, c4 = idx & 31;
            int node = node0 + r;
            if (node < n)
                out4[node * 32 + c4] = *(float4*)&sOut[r * OSTRIDE + c4 * 4];
        }
    }
}

// ---------------- classifier (also re-arms g_deg / g_pooled for next replay) -
__global__ void cls_kernel(const float* __restrict__ W1, const float* __restrict__ b1,
                           const float* __restrict__ gamma, const float* __restrict__ beta,
                           const float* __restrict__ mean, const float* __restrict__ var,
                           const float* __restrict__ W2, const float* __restrict__ b2,
                           float* __restrict__ out) {
    __shared__ float sp[384];
    __shared__ float sz[256];
    int g = blockIdx.x;
    int tid = threadIdx.x;  // 0..255
    for (int i = g * 256 + tid; i < NN; i += NG * 256) g_deg[i] = 0;
    for (int i = tid; i < 384; i += 256) sp[i] = g_pooled[g * 384 + i];
    __syncthreads();
    for (int i = tid; i < 384; i += 256) g_pooled[g * 384 + i] = 0.f;
    float acc = b1[tid];
    #pragma unroll 8
    for (int k = 0; k < 384; k++) acc += sp[k] * W1[k * 256 + tid];
    float z = (acc - mean[tid]) * rsqrtf(var[tid] + BN_EPS) * gamma[tid] + beta[tid];
    sz[tid] = fmaxf(z, 0.f);
    __syncthreads();
    if (tid < 4) {
        float o = b2[tid];
        #pragma unroll 8
        for (int k = 0; k < 256; k++) o += sz[k] * W2[k * 4 + tid];
        out[g * 4 + tid] = o;
    }
}

// ---------------- launch ----------------
extern "C" void kernel_launch(void* const* d_in, const int* in_sizes, int n_in,
                              void* d_out, int out_size) {
    const float* x     = (const float*)d_in[0];
    const int*   eidx  = (const int*)d_in[1];
    const int*   batch = (const int*)d_in[2];
    const float* l1_W1 = (const float*)d_in[3];
    const float* l1_b1 = (const float*)d_in[4];
    const float* l1_W2 = (const float*)d_in[5];
    const float* l1_b2 = (const float*)d_in[6];
    const float* l2_W1 = (const float*)d_in[7];
    const float* l2_b1 = (const float*)d_in[8];
    const float* l2_W2 = (const float*)d_in[9];
    const float* l2_b2 = (const float*)d_in[10];
    const float* l3_W1 = (const float*)d_in[11];
    const float* l3_b1 = (const float*)d_in[12];
    const float* l3_W2 = (const float*)d_in[13];
    const float* l3_b2 = (const float*)d_in[14];
    const float* c_W1  = (const float*)d_in[15];
    const float* c_b1  = (const float*)d_in[16];
    const float* bn_g  = (const float*)d_in[17];
    const float* bn_b  = (const float*)d_in[18];
    const float* bn_m  = (const float*)d_in[19];
    const float* bn_v  = (const float*)d_in[20];
    const float* c_W2  = (const float*)d_in[21];
    const float* c_b2  = (const float*)d_in[22];
    float* out = (float*)d_out;

    // smem: sWhi/sWlo (2*64*WSTRIDE) + sAhi/sAlo (2*64*ASTRIDE) + biases + batch
    const int SMEM = (2 * 64 * WSTRIDE + 2 * 64 * ASTRIDE + 256 + TILE) * 4;  // 105,984 B
    cudaFuncSetAttribute(gin_layer<8, 0, true>,
                         cudaFuncAttributeMaxDynamicSharedMemorySize, SMEM);
    cudaFuncSetAttribute(gin_layer<128, 128, true>,
                         cudaFuncAttributeMaxDynamicSharedMemorySize, SMEM);
    cudaFuncSetAttribute(gin_layer<128, 256, false>,
                         cudaFuncAttributeMaxDynamicSharedMemorySize, SMEM);

    float *bufA, *bufB;
    uint32_t (*wph)[64 * 128];
    uint32_t (*wpl)[64 * 128];
    cudaGetSymbolAddress((void**)&bufA, g_bufA);
    cudaGetSymbolAddress((void**)&bufB, g_bufB);
    cudaGetSymbolAddress((void**)&wph, g_wp_hi);
    cudaGetSymbolAddress((void**)&wpl, g_wp_lo);

    // CSR (g_deg arrives zeroed: BSS on first run, cls_kernel thereafter)
    count_kernel<<<(NE + 255) / 256, 256>>>(eidx);
    scan_kernel<<<1, 1024>>>();
    fill_kernel<<<(NE + 255) / 256, 256>>>(eidx);

    // pack all weight matrices into bf16x2 hi/lo pair images
    pack_all<<<dim3(8, 6), 256>>>(l1_W1, l1_W2, l2_W1, l2_W2, l3_W1, l3_W2);

    const int GRID = (NN + TILE - 1) / TILE;  // 782

    gin_layer<8, 0, true><<<GRID, 256, SMEM>>>(
        x, wph[0], wpl[0], l1_b1, wph[1], wpl[1], l1_b2, batch, bufA, NN);
    gin_layer<128, 128, true><<<GRID, 256, SMEM>>>(
        bufA, wph[2], wpl[2], l2_b1, wph[3], wpl[3], l2_b2, batch, bufB, NN);
    gin_layer<128, 256, false><<<GRID, 256, SMEM>>>(
        bufB, wph[4], wpl[4], l3_b1, wph[5], wpl[5], l3_b2, batch, nullptr, NN);

    cls_kernel<<<NG, 256>>>(c_W1, c_b1, bn_g, bn_b, bn_m, bn_v, c_W2, c_b2, out);
}